// round 12
// baseline (speedup 1.0000x reference)
#include <cuda_runtime.h>
#include <math.h>

#define NPTS 8192
#define DIM  128
#define CAND_MAX 1024

// ---------------- device scratch (no allocations allowed) ----------------
__device__ float         g_dist[(size_t)NPTS * NPTS];  // 256 MB distance matrix
__device__ float         g_sq[NPTS];
__device__ unsigned char g_lab[NPTS];
__device__ float         g_loss[NPTS];
__device__ float         g_accv[NPTS];
__device__ float         g_tpv[NPTS];
__device__ float         g_tnv[NPTS];
__device__ int           g_is32;

// ---------------- packed fp32x2 helpers (Blackwell FFMA2 path) -----------
__device__ __forceinline__ void fma2(unsigned long long& d,
                                     unsigned long long a,
                                     unsigned long long b) {
    asm("fma.rn.f32x2 %0, %1, %2, %0;" : "+l"(d) : "l"(a), "l"(b));
}
__device__ __forceinline__ unsigned long long pack2(float lo, float hi) {
    unsigned long long r;
    asm("mov.b64 %0, {%1, %2};" : "=l"(r) : "r"(__float_as_uint(lo)), "r"(__float_as_uint(hi)));
    return r;
}
__device__ __forceinline__ void unpack2(unsigned long long v, float& lo, float& hi) {
    unsigned a, b;
    asm("mov.b64 {%0, %1}, %2;" : "=r"(a), "=r"(b) : "l"(v));
    lo = __uint_as_float(a);
    hi = __uint_as_float(b);
}

// ---------------- dtype detection for targets (int32 vs int64) -----------
__global__ void detect_kernel(const int* __restrict__ t) {
    int local = 0;
    for (int j = threadIdx.x; j < 4096; j += blockDim.x) local |= t[2 * j + 1];
#pragma unroll
    for (int off = 16; off; off >>= 1) local |= __shfl_down_sync(0xffffffffu, local, off);
    __shared__ int s[8];
    if ((threadIdx.x & 31) == 0) s[threadIdx.x >> 5] = local;
    __syncthreads();
    if (threadIdx.x == 0) {
        int f = 0;
        for (int w = 0; w < 8; w++) f |= s[w];
        g_is32 = (f != 0);
    }
}

__global__ void conv_kernel(const void* __restrict__ t) {
    int is32 = g_is32;
    int i = blockIdx.x * blockDim.x + threadIdx.x;
    if (i < NPTS) {
        int v = is32 ? ((const int*)t)[i] : (int)(((const long long*)t)[i]);
        g_lab[i] = (unsigned char)v;
    }
}

// ---------------- squared norms ----------------
__global__ void sq_kernel(const float* __restrict__ X) {
    int i = blockIdx.x;
    int tid = threadIdx.x;  // 128 threads
    float v = X[i * DIM + tid];
    v *= v;
#pragma unroll
    for (int off = 16; off; off >>= 1) v += __shfl_down_sync(0xffffffffu, v, off);
    __shared__ float s[4];
    if ((tid & 31) == 0) s[tid >> 5] = v;
    __syncthreads();
    if (tid == 0) g_sq[i] = s[0] + s[1] + s[2] + s[3];
}

// ---------------- distance matrix: symmetric tiled fp32x2 "GEMM" ----------
__global__ void __launch_bounds__(256, 2) dist_kernel(const float* __restrict__ X) {
    __shared__ float As[16][128];
    __shared__ float Bs[16][128];

    const int t = blockIdx.x;
    int b = (int)((sqrtf(8.0f * (float)t + 1.0f) - 1.0f) * 0.5f);
    while ((b * (b + 1)) / 2 > t) b--;
    while (((b + 1) * (b + 2)) / 2 <= t) b++;
    const int by = t - (b * (b + 1)) / 2;   // row tile
    const int bx = b;                       // col tile (>= by)

    const int tid = threadIdx.x;
    const int tx = tid & 15;
    const int ty = tid >> 4;
    const int rowbase = by * 128;
    const int colbase = bx * 128;

    unsigned long long acc2[8][4];
#pragma unroll
    for (int a = 0; a < 8; a++)
#pragma unroll
        for (int c = 0; c < 4; c++) acc2[a][c] = 0ull;

    for (int k0 = 0; k0 < DIM; k0 += 16) {
#pragma unroll
        for (int r = 0; r < 2; r++) {
            int pos = tid + r * 256;
            int row = pos >> 2;
            int kc  = pos & 3;
            float4 va = *(const float4*)&X[(size_t)(rowbase + row) * DIM + k0 + kc * 4];
            As[kc * 4 + 0][row] = va.x;
            As[kc * 4 + 1][row] = va.y;
            As[kc * 4 + 2][row] = va.z;
            As[kc * 4 + 3][row] = va.w;
            float4 vb = *(const float4*)&X[(size_t)(colbase + row) * DIM + k0 + kc * 4];
            Bs[kc * 4 + 0][row] = vb.x;
            Bs[kc * 4 + 1][row] = vb.y;
            Bs[kc * 4 + 2][row] = vb.z;
            Bs[kc * 4 + 3][row] = vb.w;
        }
        __syncthreads();
#pragma unroll
        for (int kk = 0; kk < 16; kk++) {
            float ar[8], br[8];
            *(float4*)&ar[0] = *(const float4*)&As[kk][ty * 8];
            *(float4*)&ar[4] = *(const float4*)&As[kk][ty * 8 + 4];
            *(float4*)&br[0] = *(const float4*)&Bs[kk][tx * 8];
            *(float4*)&br[4] = *(const float4*)&Bs[kk][tx * 8 + 4];
            unsigned long long b2[4];
#pragma unroll
            for (int c = 0; c < 4; c++) b2[c] = pack2(br[2 * c], br[2 * c + 1]);
#pragma unroll
            for (int a = 0; a < 8; a++) {
                unsigned long long a2 = pack2(ar[a], ar[a]);
#pragma unroll
                for (int c = 0; c < 4; c++) fma2(acc2[a][c], a2, b2[c]);
            }
        }
        __syncthreads();
    }

    float sqa[8], sqb[8];
#pragma unroll
    for (int a = 0; a < 8; a++) sqa[a] = g_sq[rowbase + ty * 8 + a];
#pragma unroll
    for (int c = 0; c < 8; c++) sqb[c] = g_sq[colbase + tx * 8 + c];

    float acc[8][8];
#pragma unroll
    for (int a = 0; a < 8; a++)
#pragma unroll
        for (int c = 0; c < 4; c++) {
            float lo, hi;
            unpack2(acc2[a][c], lo, hi);
            acc[a][2 * c]     = sqrtf(fmaxf(sqa[a] + sqb[2 * c]     - 2.0f * lo, 1e-12f));
            acc[a][2 * c + 1] = sqrtf(fmaxf(sqa[a] + sqb[2 * c + 1] - 2.0f * hi, 1e-12f));
        }

#pragma unroll
    for (int a = 0; a < 8; a++) {
        int row = rowbase + ty * 8 + a;
        float4 o0 = make_float4(acc[a][0], acc[a][1], acc[a][2], acc[a][3]);
        float4 o1 = make_float4(acc[a][4], acc[a][5], acc[a][6], acc[a][7]);
        *(float4*)&g_dist[(size_t)row * NPTS + colbase + tx * 8]     = o0;
        *(float4*)&g_dist[(size_t)row * NPTS + colbase + tx * 8 + 4] = o1;
    }

    if (bx != by) {
#pragma unroll
        for (int c = 0; c < 8; c++) {
            int col = colbase + tx * 8 + c;
            float4 p0 = make_float4(acc[0][c], acc[1][c], acc[2][c], acc[3][c]);
            float4 p1 = make_float4(acc[4][c], acc[5][c], acc[6][c], acc[7][c]);
            *(float4*)&g_dist[(size_t)col * NPTS + rowbase + ty * 8]     = p0;
            *(float4*)&g_dist[(size_t)col * NPTS + rowbase + ty * 8 + 4] = p1;
        }
    }
}

// ---------------- per-row kernel: pivot + gather + exact small-select ------
// Row lives in registers (32 floats/thread). Pivot = min over warps of each
// warp's 17th-smallest thread-min. Valid upper bound on the true 17th value:
// in the witness warp, the 17 lanes with rank<=16 each hold a value <= pivot.
// Computed with 31 independent shfl_xor compares per warp (no serial chain).
__global__ void __launch_bounds__(256) row_kernel() {
    const int i = blockIdx.x;
    const int tid = threadIdx.x;
    const int lane = tid & 31;
    const int wid = tid >> 5;
    const float INF = __int_as_float(0x7f800000);

    __shared__ int   swarr[8];
    __shared__ float cand_v[CAND_MAX];
    __shared__ int   cand_j[CAND_MAX];
    __shared__ int   s_cnt;
    __shared__ int   s_piv_bits;
    __shared__ float s_thr;
    __shared__ float sps[8], sns[8], sfpd[8];
    __shared__ int   scp[8], scn[8], sfp[8], san[8];

    if (tid == 0) { s_cnt = 0; s_piv_bits = 0x7f800000; }

    // ---- load row into registers: v[c*4+k] = row[c*1024 + 4*tid + k] ----
    float v[32];
    const float4* drow4 = (const float4*)(g_dist + (size_t)i * NPTS);
#pragma unroll
    for (int c = 0; c < 8; c++) {
        float4 t4 = drow4[c * 256 + tid];
        v[c * 4 + 0] = t4.x;
        v[c * 4 + 1] = t4.y;
        v[c * 4 + 2] = t4.z;
        v[c * 4 + 3] = t4.w;
    }
    // diagonal -> +inf (owned by thread (i&1023)>>2, slot (i>>10)*4 + (i&3))
    if (tid == ((i & 1023) >> 2))
        v[((i >> 10) << 2) + (i & 3)] = INF;

    // ---- per-thread min ----
    float mn = v[0];
#pragma unroll
    for (int c = 1; c < 32; c++) mn = fminf(mn, v[c]);
    __syncthreads();  // s_cnt/s_piv_bits init visible before atomics below

    // ---- per-warp rank of mn among the warp's 32 mins (31 indep shfls) ----
    {
        int r = 0;
#pragma unroll
        for (int o = 1; o < 32; o++) {
            float ov = __shfl_xor_sync(0xffffffffu, mn, o);
            int ol = lane ^ o;
            r += (ov < mn) || (ov == mn && ol < lane);
        }
        // lane holding the warp's 17th-smallest min proposes it as pivot
        if (r == 16) atomicMin(&s_piv_bits, (int)__float_as_uint(mn));
    }
    __syncthreads();
    const float pivot = __uint_as_float((unsigned)s_piv_bits);

    // ---- gather candidates (v <= pivot); shfl uses the ballot mask m ----
#pragma unroll
    for (int c = 0; c < 8; c++) {
#pragma unroll
        for (int k = 0; k < 4; k++) {
            float val = v[c * 4 + k];
            bool sel = (val <= pivot);
            unsigned m = __ballot_sync(0xffffffffu, sel);
            if (sel) {
                int leader = __ffs(m) - 1;
                int base = 0;
                if (lane == leader) base = atomicAdd(&s_cnt, __popc(m));
                base = __shfl_sync(m, base, leader);
                int pos = base + __popc(m & ((1u << lane) - 1));
                if (pos < CAND_MAX) {
                    cand_v[pos] = val;
                    cand_j[pos] = c * 1024 + 4 * tid + k;
                }
            }
        }
    }
    __syncthreads();
    const int cnt = s_cnt;

    if (cnt <= CAND_MAX) {
        // exact 17th smallest among candidates by (value, index) rank
        for (int t = tid; t < cnt; t += 256) {
            float mv = cand_v[t];
            int mj = cand_j[t];
            int r = 0;
            for (int s = 0; s < cnt; s++) {
                float ov = cand_v[s];
                r += (ov < mv) || (ov == mv && cand_j[s] < mj);
            }
            if (r == 16) s_thr = mv;  // unique by (value, j)
        }
    } else {
        // unconditional-correctness fallback: exact bitwise select (rare)
        unsigned cur = 0;
        int rank = 17;
        for (int bit = 30; bit >= 0; bit--) {
            unsigned mid = cur | (1u << bit);
            int c0 = 0;
#pragma unroll
            for (int c = 0; c < 32; c++) {
                unsigned bits = __float_as_uint(v[c]);
                c0 += (bits >= cur && bits < mid) ? 1 : 0;
            }
            c0 = __reduce_add_sync(0xffffffffu, c0);
            if (lane == 0) swarr[wid] = c0;
            __syncthreads();
            int tot = 0;
            for (int w = 0; w < 8; w++) tot += swarr[w];
            if (tot < rank) { rank -= tot; cur = mid; }
            __syncthreads();
        }
        if (tid == 0) s_thr = __uint_as_float(cur);
    }
    __syncthreads();
    const float thr = s_thr;
    const int myl = g_lab[i];

    // ---- masked sums from registers (strict dist < thr), deterministic ----
    float ps = 0.0f, ns = 0.0f, fpd = 0.0f;
    int cp = 0, cn = 0, fp = NPTS, anyneg = 0;
#pragma unroll
    for (int c = 0; c < 8; c++) {
        uchar4 l4 = *(const uchar4*)&g_lab[c * 1024 + 4 * tid];
        unsigned char ll[4] = {l4.x, l4.y, l4.z, l4.w};
#pragma unroll
        for (int k = 0; k < 4; k++) {
            int j = c * 1024 + 4 * tid + k;
            if (j == i) continue;
            float dv = v[c * 4 + k];
            bool below = dv < thr;
            if (ll[k] == myl) {
                if (j < fp) { fp = j; fpd = dv; }
                if (below) { ps += expf(-dv); cp++; }
            } else {
                anyneg = 1;
                if (below) { ns += expf(-dv); cn++; }
            }
        }
    }
#pragma unroll
    for (int off = 16; off; off >>= 1) {
        ps += __shfl_down_sync(0xffffffffu, ps, off);
        ns += __shfl_down_sync(0xffffffffu, ns, off);
        cp += __shfl_down_sync(0xffffffffu, cp, off);
        cn += __shfl_down_sync(0xffffffffu, cn, off);
        int ofp = __shfl_down_sync(0xffffffffu, fp, off);
        float ofpd = __shfl_down_sync(0xffffffffu, fpd, off);
        if (ofp < fp) { fp = ofp; fpd = ofpd; }
        anyneg |= __shfl_down_sync(0xffffffffu, anyneg, off);
    }
    if (lane == 0) {
        sps[wid] = ps; sns[wid] = ns; scp[wid] = cp; scn[wid] = cn;
        sfp[wid] = fp; sfpd[wid] = fpd; san[wid] = anyneg;
    }
    __syncthreads();
    if (tid == 0) {
        ps = 0; ns = 0; cp = 0; cn = 0; fp = NPTS; fpd = 0; anyneg = 0;
        for (int w = 0; w < 8; w++) {
            ps += sps[w]; ns += sns[w]; cp += scp[w]; cn += scn[w];
            if (sfp[w] < fp) { fp = sfp[w]; fpd = sfpd[w]; }
            anyneg |= san[w];
        }
        bool haspos = (fp < NPTS);
        bool validr = haspos && (anyneg != 0);
        float pos_eff = (cp == 0) ? (haspos ? expf(-fpd) : 1.0f) : ps;
        float loss_i = validr ? logf((pos_eff + ns) / pos_eff) : 0.0f;
        int cpa = (cp == 0) ? 1 : cp;
        g_loss[i] = loss_i;
        g_accv[i] = (validr && cpa > cn) ? 1.0f : 0.0f;
        g_tpv[i]  = validr ? (float)cp : 0.0f;
        g_tnv[i]  = validr ? (float)cn : 0.0f;
    }
}

// ---------------- deterministic final reduction ----------------
__global__ void finalize_kernel(float* __restrict__ out) {
    __shared__ float s0[256], s1[256], s2[256], s3[256];
    int tid = threadIdx.x;
    float a = 0, b = 0, c = 0, d = 0;
    for (int j = tid; j < NPTS; j += 256) {
        a += g_loss[j]; b += g_accv[j]; c += g_tpv[j]; d += g_tnv[j];
    }
    s0[tid] = a; s1[tid] = b; s2[tid] = c; s3[tid] = d;
    __syncthreads();
    for (int off = 128; off; off >>= 1) {
        if (tid < off) {
            s0[tid] += s0[tid + off];
            s1[tid] += s1[tid + off];
            s2[tid] += s2[tid + off];
            s3[tid] += s3[tid + off];
        }
        __syncthreads();
    }
    if (tid == 0) {
        const float inv = 1.0f / (float)NPTS;
        out[0] = s0[0] * inv;  // loss
        out[1] = s1[0] * inv;  // accuracy
        out[2] = s2[0] * inv;  // tp
        out[3] = s3[0] * inv;  // tn
    }
}

extern "C" void kernel_launch(void* const* d_in, const int* in_sizes, int n_in,
                              void* d_out, int out_size) {
    const float* X = (const float*)d_in[0];
    const void* T = d_in[1];
    float* out = (float*)d_out;
    (void)in_sizes; (void)n_in; (void)out_size;

    detect_kernel<<<1, 256>>>((const int*)T);
    conv_kernel<<<(NPTS + 255) / 256, 256>>>(T);
    sq_kernel<<<NPTS, 128>>>(X);
    const int ntiles = (NPTS / 128) * (NPTS / 128 + 1) / 2;  // 2080 triangular tiles
    dist_kernel<<<ntiles, 256>>>(X);
    row_kernel<<<NPTS, 256>>>();
    finalize_kernel<<<1, 256>>>(out);
}

// round 13
// speedup vs baseline: 1.2199x; 1.2199x over previous
#include <cuda_runtime.h>
#include <math.h>

#define NPTS 8192
#define DIM  128
#define CAND_MAX 1024

// ---------------- device scratch (no allocations allowed) ----------------
__device__ float         g_dist[(size_t)NPTS * NPTS];  // 256 MB distance matrix
__device__ float         g_sq[NPTS];
__device__ unsigned char g_lab[NPTS];
__device__ float         g_loss[NPTS];
__device__ float         g_accv[NPTS];
__device__ float         g_tpv[NPTS];
__device__ float         g_tnv[NPTS];
__device__ int           g_is32;

// ---------------- packed fp32x2 helpers (Blackwell FFMA2 path) -----------
__device__ __forceinline__ void fma2(unsigned long long& d,
                                     unsigned long long a,
                                     unsigned long long b) {
    asm("fma.rn.f32x2 %0, %1, %2, %0;" : "+l"(d) : "l"(a), "l"(b));
}
__device__ __forceinline__ unsigned long long pack2(float lo, float hi) {
    unsigned long long r;
    asm("mov.b64 %0, {%1, %2};" : "=l"(r) : "r"(__float_as_uint(lo)), "r"(__float_as_uint(hi)));
    return r;
}
__device__ __forceinline__ void unpack2(unsigned long long v, float& lo, float& hi) {
    unsigned a, b;
    asm("mov.b64 {%0, %1}, %2;" : "=r"(a), "=r"(b) : "l"(v));
    lo = __uint_as_float(a);
    hi = __uint_as_float(b);
}

// ---------------- dtype detection for targets (int32 vs int64) -----------
__global__ void detect_kernel(const int* __restrict__ t) {
    int local = 0;
    for (int j = threadIdx.x; j < 4096; j += blockDim.x) local |= t[2 * j + 1];
#pragma unroll
    for (int off = 16; off; off >>= 1) local |= __shfl_down_sync(0xffffffffu, local, off);
    __shared__ int s[8];
    if ((threadIdx.x & 31) == 0) s[threadIdx.x >> 5] = local;
    __syncthreads();
    if (threadIdx.x == 0) {
        int f = 0;
        for (int w = 0; w < 8; w++) f |= s[w];
        g_is32 = (f != 0);
    }
}

__global__ void conv_kernel(const void* __restrict__ t) {
    int is32 = g_is32;
    int i = blockIdx.x * blockDim.x + threadIdx.x;
    if (i < NPTS) {
        int v = is32 ? ((const int*)t)[i] : (int)(((const long long*)t)[i]);
        g_lab[i] = (unsigned char)v;
    }
}

// ---------------- squared norms ----------------
__global__ void sq_kernel(const float* __restrict__ X) {
    int i = blockIdx.x;
    int tid = threadIdx.x;  // 128 threads
    float v = X[i * DIM + tid];
    v *= v;
#pragma unroll
    for (int off = 16; off; off >>= 1) v += __shfl_down_sync(0xffffffffu, v, off);
    __shared__ float s[4];
    if ((tid & 31) == 0) s[tid >> 5] = v;
    __syncthreads();
    if (tid == 0) g_sq[i] = s[0] + s[1] + s[2] + s[3];
}

// ---------------- distance matrix: symmetric tiled fp32x2 "GEMM" ----------
__global__ void __launch_bounds__(256, 2) dist_kernel(const float* __restrict__ X) {
    __shared__ float As[16][128];
    __shared__ float Bs[16][128];

    const int t = blockIdx.x;
    int b = (int)((sqrtf(8.0f * (float)t + 1.0f) - 1.0f) * 0.5f);
    while ((b * (b + 1)) / 2 > t) b--;
    while (((b + 1) * (b + 2)) / 2 <= t) b++;
    const int by = t - (b * (b + 1)) / 2;   // row tile
    const int bx = b;                       // col tile (>= by)

    const int tid = threadIdx.x;
    const int tx = tid & 15;
    const int ty = tid >> 4;
    const int rowbase = by * 128;
    const int colbase = bx * 128;

    unsigned long long acc2[8][4];
#pragma unroll
    for (int a = 0; a < 8; a++)
#pragma unroll
        for (int c = 0; c < 4; c++) acc2[a][c] = 0ull;

    for (int k0 = 0; k0 < DIM; k0 += 16) {
#pragma unroll
        for (int r = 0; r < 2; r++) {
            int pos = tid + r * 256;
            int row = pos >> 2;
            int kc  = pos & 3;
            float4 va = *(const float4*)&X[(size_t)(rowbase + row) * DIM + k0 + kc * 4];
            As[kc * 4 + 0][row] = va.x;
            As[kc * 4 + 1][row] = va.y;
            As[kc * 4 + 2][row] = va.z;
            As[kc * 4 + 3][row] = va.w;
            float4 vb = *(const float4*)&X[(size_t)(colbase + row) * DIM + k0 + kc * 4];
            Bs[kc * 4 + 0][row] = vb.x;
            Bs[kc * 4 + 1][row] = vb.y;
            Bs[kc * 4 + 2][row] = vb.z;
            Bs[kc * 4 + 3][row] = vb.w;
        }
        __syncthreads();
#pragma unroll
        for (int kk = 0; kk < 16; kk++) {
            float ar[8], br[8];
            *(float4*)&ar[0] = *(const float4*)&As[kk][ty * 8];
            *(float4*)&ar[4] = *(const float4*)&As[kk][ty * 8 + 4];
            *(float4*)&br[0] = *(const float4*)&Bs[kk][tx * 8];
            *(float4*)&br[4] = *(const float4*)&Bs[kk][tx * 8 + 4];
            unsigned long long b2[4];
#pragma unroll
            for (int c = 0; c < 4; c++) b2[c] = pack2(br[2 * c], br[2 * c + 1]);
#pragma unroll
            for (int a = 0; a < 8; a++) {
                unsigned long long a2 = pack2(ar[a], ar[a]);
#pragma unroll
                for (int c = 0; c < 4; c++) fma2(acc2[a][c], a2, b2[c]);
            }
        }
        __syncthreads();
    }

    float sqa[8], sqb[8];
#pragma unroll
    for (int a = 0; a < 8; a++) sqa[a] = g_sq[rowbase + ty * 8 + a];
#pragma unroll
    for (int c = 0; c < 8; c++) sqb[c] = g_sq[colbase + tx * 8 + c];

    float acc[8][8];
#pragma unroll
    for (int a = 0; a < 8; a++)
#pragma unroll
        for (int c = 0; c < 4; c++) {
            float lo, hi;
            unpack2(acc2[a][c], lo, hi);
            acc[a][2 * c]     = sqrtf(fmaxf(sqa[a] + sqb[2 * c]     - 2.0f * lo, 1e-12f));
            acc[a][2 * c + 1] = sqrtf(fmaxf(sqa[a] + sqb[2 * c + 1] - 2.0f * hi, 1e-12f));
        }

#pragma unroll
    for (int a = 0; a < 8; a++) {
        int row = rowbase + ty * 8 + a;
        float4 o0 = make_float4(acc[a][0], acc[a][1], acc[a][2], acc[a][3]);
        float4 o1 = make_float4(acc[a][4], acc[a][5], acc[a][6], acc[a][7]);
        *(float4*)&g_dist[(size_t)row * NPTS + colbase + tx * 8]     = o0;
        *(float4*)&g_dist[(size_t)row * NPTS + colbase + tx * 8 + 4] = o1;
    }

    if (bx != by) {
#pragma unroll
        for (int c = 0; c < 8; c++) {
            int col = colbase + tx * 8 + c;
            float4 p0 = make_float4(acc[0][c], acc[1][c], acc[2][c], acc[3][c]);
            float4 p1 = make_float4(acc[4][c], acc[5][c], acc[6][c], acc[7][c]);
            *(float4*)&g_dist[(size_t)col * NPTS + rowbase + ty * 8]     = p0;
            *(float4*)&g_dist[(size_t)col * NPTS + rowbase + ty * 8 + 4] = p1;
        }
    }
}

// ---------------- per-row kernel: tight parallel pivot + gather + select ---
// Pivot = EXACT 17th smallest of the 256 per-thread minima, computed in two
// parallel levels: (1) warp rank via 31 independent shfl_xor compares; lanes
// with warp-rank<17 deposit into a 136-slot array (the global-17 smallest mins
// all have warp-rank<=16, so the 136-set contains them); (2) 136 threads rank
// within the 136-set; rank 16 is the pivot. Tight pivot => small candidate
// set => cheap exact rank-scan.
__global__ void __launch_bounds__(256) row_kernel() {
    const int i = blockIdx.x;
    const int tid = threadIdx.x;
    const int lane = tid & 31;
    const int wid = tid >> 5;
    const float INF = __int_as_float(0x7f800000);

    __shared__ int   swarr[8];
    __shared__ float s_pmin[136];     // 8 warps * 17 top mins
    __shared__ float cand_v[CAND_MAX];
    __shared__ int   cand_j[CAND_MAX];
    __shared__ int   s_cnt;
    __shared__ float s_pivot;
    __shared__ float s_thr;
    __shared__ float sps[8], sns[8], sfpd[8];
    __shared__ int   scp[8], scn[8], sfp[8], san[8];

    if (tid == 0) s_cnt = 0;

    // ---- load row into registers: v[c*4+k] = row[c*1024 + 4*tid + k] ----
    float v[32];
    const float4* drow4 = (const float4*)(g_dist + (size_t)i * NPTS);
#pragma unroll
    for (int c = 0; c < 8; c++) {
        float4 t4 = drow4[c * 256 + tid];
        v[c * 4 + 0] = t4.x;
        v[c * 4 + 1] = t4.y;
        v[c * 4 + 2] = t4.z;
        v[c * 4 + 3] = t4.w;
    }
    // diagonal -> +inf (owned by thread (i&1023)>>2, slot (i>>10)*4 + (i&3))
    if (tid == ((i & 1023) >> 2))
        v[((i >> 10) << 2) + (i & 3)] = INF;

    // ---- per-thread min ----
    float mn = v[0];
#pragma unroll
    for (int c = 1; c < 32; c++) mn = fminf(mn, v[c]);

    // ---- level 1: warp rank of mn (31 independent shfl_xor compares) ----
    {
        int r = 0;
#pragma unroll
        for (int o = 1; o < 32; o++) {
            float ov = __shfl_xor_sync(0xffffffffu, mn, o);
            int ol = lane ^ o;
            r += (ov < mn) || (ov == mn && ol < lane);
        }
        if (r < 17) s_pmin[wid * 17 + r] = mn;  // unique slot per (warp, rank)
    }
    __syncthreads();

    // ---- level 2: exact 17th among the 136 gathered mins ----
    if (tid < 136) {
        float val = s_pmin[tid];
        int r = 0;
        for (int s = 0; s < 136; s++) {
            float ov = s_pmin[s];
            r += (ov < val) || (ov == val && s < tid);
        }
        if (r == 16) s_pivot = val;  // exact 17th-smallest thread-min
    }
    __syncthreads();
    const float pivot = s_pivot;

    // ---- gather candidates (v <= pivot); shfl uses the ballot mask m ----
#pragma unroll
    for (int c = 0; c < 8; c++) {
#pragma unroll
        for (int k = 0; k < 4; k++) {
            float val = v[c * 4 + k];
            bool sel = (val <= pivot);
            unsigned m = __ballot_sync(0xffffffffu, sel);
            if (sel) {
                int leader = __ffs(m) - 1;
                int base = 0;
                if (lane == leader) base = atomicAdd(&s_cnt, __popc(m));
                base = __shfl_sync(m, base, leader);
                int pos = base + __popc(m & ((1u << lane) - 1));
                if (pos < CAND_MAX) {
                    cand_v[pos] = val;
                    cand_j[pos] = c * 1024 + 4 * tid + k;
                }
            }
        }
    }
    __syncthreads();
    const int cnt = s_cnt;

    if (cnt <= CAND_MAX) {
        // exact 17th smallest among candidates by (value, index) rank
        for (int t = tid; t < cnt; t += 256) {
            float mv = cand_v[t];
            int mj = cand_j[t];
            int r = 0;
            for (int s = 0; s < cnt; s++) {
                float ov = cand_v[s];
                r += (ov < mv) || (ov == mv && cand_j[s] < mj);
            }
            if (r == 16) s_thr = mv;  // unique by (value, j)
        }
    } else {
        // unconditional-correctness fallback: exact bitwise select (rare)
        unsigned cur = 0;
        int rank = 17;
        for (int bit = 30; bit >= 0; bit--) {
            unsigned mid = cur | (1u << bit);
            int c0 = 0;
#pragma unroll
            for (int c = 0; c < 32; c++) {
                unsigned bits = __float_as_uint(v[c]);
                c0 += (bits >= cur && bits < mid) ? 1 : 0;
            }
            c0 = __reduce_add_sync(0xffffffffu, c0);
            if (lane == 0) swarr[wid] = c0;
            __syncthreads();
            int tot = 0;
            for (int w = 0; w < 8; w++) tot += swarr[w];
            if (tot < rank) { rank -= tot; cur = mid; }
            __syncthreads();
        }
        if (tid == 0) s_thr = __uint_as_float(cur);
    }
    __syncthreads();
    const float thr = s_thr;
    const int myl = g_lab[i];

    // ---- masked sums from registers (strict dist < thr), deterministic ----
    float ps = 0.0f, ns = 0.0f, fpd = 0.0f;
    int cp = 0, cn = 0, fp = NPTS, anyneg = 0;
#pragma unroll
    for (int c = 0; c < 8; c++) {
        uchar4 l4 = *(const uchar4*)&g_lab[c * 1024 + 4 * tid];
        unsigned char ll[4] = {l4.x, l4.y, l4.z, l4.w};
#pragma unroll
        for (int k = 0; k < 4; k++) {
            int j = c * 1024 + 4 * tid + k;
            if (j == i) continue;
            float dv = v[c * 4 + k];
            bool below = dv < thr;
            if (ll[k] == myl) {
                if (j < fp) { fp = j; fpd = dv; }
                if (below) { ps += expf(-dv); cp++; }
            } else {
                anyneg = 1;
                if (below) { ns += expf(-dv); cn++; }
            }
        }
    }
#pragma unroll
    for (int off = 16; off; off >>= 1) {
        ps += __shfl_down_sync(0xffffffffu, ps, off);
        ns += __shfl_down_sync(0xffffffffu, ns, off);
        cp += __shfl_down_sync(0xffffffffu, cp, off);
        cn += __shfl_down_sync(0xffffffffu, cn, off);
        int ofp = __shfl_down_sync(0xffffffffu, fp, off);
        float ofpd = __shfl_down_sync(0xffffffffu, fpd, off);
        if (ofp < fp) { fp = ofp; fpd = ofpd; }
        anyneg |= __shfl_down_sync(0xffffffffu, anyneg, off);
    }
    if (lane == 0) {
        sps[wid] = ps; sns[wid] = ns; scp[wid] = cp; scn[wid] = cn;
        sfp[wid] = fp; sfpd[wid] = fpd; san[wid] = anyneg;
    }
    __syncthreads();
    if (tid == 0) {
        ps = 0; ns = 0; cp = 0; cn = 0; fp = NPTS; fpd = 0; anyneg = 0;
        for (int w = 0; w < 8; w++) {
            ps += sps[w]; ns += sns[w]; cp += scp[w]; cn += scn[w];
            if (sfp[w] < fp) { fp = sfp[w]; fpd = sfpd[w]; }
            anyneg |= san[w];
        }
        bool haspos = (fp < NPTS);
        bool validr = haspos && (anyneg != 0);
        float pos_eff = (cp == 0) ? (haspos ? expf(-fpd) : 1.0f) : ps;
        float loss_i = validr ? logf((pos_eff + ns) / pos_eff) : 0.0f;
        int cpa = (cp == 0) ? 1 : cp;
        g_loss[i] = loss_i;
        g_accv[i] = (validr && cpa > cn) ? 1.0f : 0.0f;
        g_tpv[i]  = validr ? (float)cp : 0.0f;
        g_tnv[i]  = validr ? (float)cn : 0.0f;
    }
}

// ---------------- deterministic final reduction ----------------
__global__ void finalize_kernel(float* __restrict__ out) {
    __shared__ float s0[256], s1[256], s2[256], s3[256];
    int tid = threadIdx.x;
    float a = 0, b = 0, c = 0, d = 0;
    for (int j = tid; j < NPTS; j += 256) {
        a += g_loss[j]; b += g_accv[j]; c += g_tpv[j]; d += g_tnv[j];
    }
    s0[tid] = a; s1[tid] = b; s2[tid] = c; s3[tid] = d;
    __syncthreads();
    for (int off = 128; off; off >>= 1) {
        if (tid < off) {
            s0[tid] += s0[tid + off];
            s1[tid] += s1[tid + off];
            s2[tid] += s2[tid + off];
            s3[tid] += s3[tid + off];
        }
        __syncthreads();
    }
    if (tid == 0) {
        const float inv = 1.0f / (float)NPTS;
        out[0] = s0[0] * inv;  // loss
        out[1] = s1[0] * inv;  // accuracy
        out[2] = s2[0] * inv;  // tp
        out[3] = s3[0] * inv;  // tn
    }
}

extern "C" void kernel_launch(void* const* d_in, const int* in_sizes, int n_in,
                              void* d_out, int out_size) {
    const float* X = (const float*)d_in[0];
    const void* T = d_in[1];
    float* out = (float*)d_out;
    (void)in_sizes; (void)n_in; (void)out_size;

    detect_kernel<<<1, 256>>>((const int*)T);
    conv_kernel<<<(NPTS + 255) / 256, 256>>>(T);
    sq_kernel<<<NPTS, 128>>>(X);
    const int ntiles = (NPTS / 128) * (NPTS / 128 + 1) / 2;  // 2080 triangular tiles
    dist_kernel<<<ntiles, 256>>>(X);
    row_kernel<<<NPTS, 256>>>();
    finalize_kernel<<<1, 256>>>(out);
}